// round 7
// baseline (speedup 1.0000x reference)
#include <cuda_runtime.h>

// Fixed problem shape
#define BB 256
#define TT 4096
#define CC 16
#define HH 20
#define GG 60
#define K  8              // steps per chunk
#define NC (TT / K)       // 512 chunks

typedef unsigned long long u64;

__device__ __forceinline__ u64 pack2(float a, float b) {
    u64 r; asm("mov.b64 %0,{%1,%2};" : "=l"(r) : "f"(a), "f"(b)); return r;
}
__device__ __forceinline__ void fma2(u64& d, u64 a, u64 b) {
    asm("fma.rn.f32x2 %0,%1,%2,%0;" : "+l"(d) : "l"(a), "l"(b));
}
__device__ __forceinline__ float hsum2(u64 v) {
    float x, y; asm("mov.b64 {%0,%1},%2;" : "=f"(x), "=f"(y) : "l"(v)); return x + y;
}
__device__ __forceinline__ float tanha(float x) {
    float y; asm("tanh.approx.f32 %0,%1;" : "=f"(y) : "f"(x)); return y;
}
__device__ __forceinline__ float siga(float x) {
    return fmaf(tanha(x * 0.5f), 0.5f, 0.5f);
}

// ---------------------------------------------------------------------------
// Fully fused 2-layer GRU: 2 warps per batch, 4 warps per block (2 batches),
// 128 blocks -> one block per SM, EVERY WARP SOLO on its own SMSP.
//
//   w0 = L0'(A) S0 : layer-0 recurrence + fused gx1 (lagged ONE STEP so the
//                    gx1 dot is chain-independent filler for the MUFU gaps)
//   w1 = L0'(B) S1
//   w2 = L1'(A) S2 : layer-1 recurrence + fused gx0 (chain-independent) +
//                    x prefetch + output head
//   w3 = L1'(B) S3
//
// Iteration c:  L1' computes gx0 chunk c (from s_x) and L1 chunk c-2 (from
// s_gx1); L0' computes L0 chunk c-1 (from s_gx0) producing gx1 chunk c-1.
// 2-deep rings, one __syncthreads per iteration (all warps, every iter).
// Per-step math identical to round 6 (single f32x2 accumulator per gate).
// ---------------------------------------------------------------------------
__global__ void __launch_bounds__(128, 1)
fused_gru_kernel(const float* __restrict__ x,      // [B,T,C]
                 const float* __restrict__ h0in,   // [B,2,H]
                 const float* __restrict__ W_ih0, const float* __restrict__ W_hh0,
                 const float* __restrict__ b_ih0, const float* __restrict__ b_hh0,
                 const float* __restrict__ W_ih1, const float* __restrict__ W_hh1,
                 const float* __restrict__ b_ih1, const float* __restrict__ b_hh1,
                 const float* __restrict__ W_o,   const float* __restrict__ b_o,
                 float* __restrict__ out)          // o[B*T] then h_n[B,2,H]
{
    __shared__ float s_x  [2][2][K][CC];   // 4 KB
    __shared__ float s_gx0[2][2][K][GG];   // 15 KB
    __shared__ float s_gx1[2][2][K][GG];   // 15 KB

    const int tid = threadIdx.x;
    const int w   = tid >> 5;
    const int i   = tid & 31;
    const bool act = (i < HH);
    const unsigned FULL = 0xFFFFFFFFu;

    const int rc = w >> 1;     // 0 = L0' (L0 + gx1),  1 = L1' (L1 + gx0 + head)
    const int bs = w & 1;
    const int b  = blockIdx.x * 2 + bs;
    const float* xb = x + (size_t)b * TT * CC;

    // ---- prime x chunk 0 (L1' warps): K*CC = 128 floats = 32 float4 --------
    if (rc == 1)
        ((float4*)&s_x[bs][0][0][0])[i] = ((const float4*)xb)[i];
    __syncthreads();

    if (rc == 0) {
        // ================= L0' : layer-0 recurrence + fused gx1 ==============
        u64 wh[30];   // W_hh0 rows (r,z,n) for unit i, packed over j
        u64 wi[30];   // W_ih1 rows, packed over j
        float br = 0.f, bz = 0.f, bn = 0.f;       // b_hh0
        float cr_ = 0.f, cz_ = 0.f, cn_ = 0.f;    // b_ih1
        float h = 0.f;
#pragma unroll
        for (int g = 0; g < 3; ++g)
#pragma unroll
            for (int k = 0; k < 10; ++k) {
                wh[g * 10 + k] = act ? pack2(W_hh0[(g * HH + i) * HH + 2 * k],
                                             W_hh0[(g * HH + i) * HH + 2 * k + 1])
                                     : pack2(0.f, 0.f);
                wi[g * 10 + k] = act ? pack2(W_ih1[(g * HH + i) * HH + 2 * k],
                                             W_ih1[(g * HH + i) * HH + 2 * k + 1])
                                     : pack2(0.f, 0.f);
            }
        if (act) {
            br = b_hh0[i]; bz = b_hh0[HH + i]; bn = b_hh0[2 * HH + i];
            cr_ = b_ih1[i]; cz_ = b_ih1[HH + i]; cn_ = b_ih1[2 * HH + i];
            h = h0in[(b * 2 + 0) * HH + i];
        }
        u64 hp[10];
#pragma unroll
        for (int k = 0; k < 10; ++k)
            hp[k] = pack2(__shfl_sync(FULL, h, 2 * k),
                          __shfl_sync(FULL, h, 2 * k + 1));

        for (int c = 0; c < NC + 2; ++c) {
            const int cc = c - 1;
            if (cc >= 0 && cc < NC) {
                const float* gx = &s_gx0[bs][cc & 1][0][0];
                float* go = &s_gx1[bs][cc & 1][0][0];
#pragma unroll 2
                for (int s = 0; s < K; ++s) {
                    float gr = 0.f, gz = 0.f, gn = 0.f;
                    if (act) {
                        gr = gx[s * GG + i];
                        gz = gx[s * GG + HH + i];
                        gn = gx[s * GG + 2 * HH + i];
                    }
                    // layer-0 recurrence dot (critical chain) — reads hp = h0[s-1]
                    u64 ar = pack2(br, 0.f), az = pack2(bz, 0.f), an = pack2(bn, 0.f);
#pragma unroll
                    for (int k = 0; k < 10; ++k) {
                        fma2(ar, wh[k],      hp[k]);
                        fma2(az, wh[10 + k], hp[k]);
                        fma2(an, wh[20 + k], hp[k]);
                    }
                    // fused gx1 for step s-1 — ALSO reads hp = h0[s-1], fully
                    // independent of the chain above: fills the MUFU gaps.
                    if (s > 0) {
                        u64 qr = pack2(cr_, 0.f), qz = pack2(cz_, 0.f), qn = pack2(cn_, 0.f);
#pragma unroll
                        for (int k = 0; k < 10; ++k) {
                            fma2(qr, wi[k],      hp[k]);
                            fma2(qz, wi[10 + k], hp[k]);
                            fma2(qn, wi[20 + k], hp[k]);
                        }
                        if (act) {
                            go[(s - 1) * GG + i]          = hsum2(qr);
                            go[(s - 1) * GG + HH + i]     = hsum2(qz);
                            go[(s - 1) * GG + 2 * HH + i] = hsum2(qn);
                        }
                    }
                    const float r = siga(gr + hsum2(ar));
                    const float z = siga(gz + hsum2(az));
                    const float n = tanha(fmaf(r, hsum2(an), gn));
                    h = fmaf(z, h - n, n);
#pragma unroll
                    for (int k = 0; k < 10; ++k)
                        hp[k] = pack2(__shfl_sync(FULL, h, 2 * k),
                                      __shfl_sync(FULL, h, 2 * k + 1));
                }
                // flush gx1 for step K-1 (hp now holds h0[K-1])
                {
                    u64 qr = pack2(cr_, 0.f), qz = pack2(cz_, 0.f), qn = pack2(cn_, 0.f);
#pragma unroll
                    for (int k = 0; k < 10; ++k) {
                        fma2(qr, wi[k],      hp[k]);
                        fma2(qz, wi[10 + k], hp[k]);
                        fma2(qn, wi[20 + k], hp[k]);
                    }
                    if (act) {
                        go[(K - 1) * GG + i]          = hsum2(qr);
                        go[(K - 1) * GG + HH + i]     = hsum2(qz);
                        go[(K - 1) * GG + 2 * HH + i] = hsum2(qn);
                    }
                }
            }
            __syncthreads();
        }
        if (act) out[(size_t)BB * TT + (b * 2 + 0) * HH + i] = h;

    } else {
        // ======== L1' : layer-1 recurrence + fused gx0 + x prefetch + head ===
        u64 wh[30];   // W_hh1
        u64 wp[24];   // W_ih0 (gx0), packed over c
        float br = 0.f, bz = 0.f, bn = 0.f;       // b_hh1
        float xr_ = 0.f, xz_ = 0.f, xn_ = 0.f;    // b_ih0
        float h = 0.f, wo = 0.f;
#pragma unroll
        for (int g = 0; g < 3; ++g) {
#pragma unroll
            for (int k = 0; k < 10; ++k)
                wh[g * 10 + k] = act ? pack2(W_hh1[(g * HH + i) * HH + 2 * k],
                                             W_hh1[(g * HH + i) * HH + 2 * k + 1])
                                     : pack2(0.f, 0.f);
#pragma unroll
            for (int k = 0; k < 8; ++k)
                wp[g * 8 + k] = act ? pack2(W_ih0[(g * HH + i) * CC + 2 * k],
                                            W_ih0[(g * HH + i) * CC + 2 * k + 1])
                                    : pack2(0.f, 0.f);
        }
        if (act) {
            br = b_hh1[i]; bz = b_hh1[HH + i]; bn = b_hh1[2 * HH + i];
            xr_ = b_ih0[i]; xz_ = b_ih0[HH + i]; xn_ = b_ih0[2 * HH + i];
            h = h0in[(b * 2 + 1) * HH + i];
            wo = W_o[i];
        }
        const float bo = b_o[0];
        float* ob = out + (size_t)b * TT;

        u64 hp[10];
#pragma unroll
        for (int k = 0; k < 10; ++k)
            hp[k] = pack2(__shfl_sync(FULL, h, 2 * k),
                          __shfl_sync(FULL, h, 2 * k + 1));

        for (int c = 0; c < NC + 2; ++c) {
            float4 xpref;
            const bool pf = (c + 1 < NC);
            if (pf) xpref = ((const float4*)(xb + (size_t)(c + 1) * K * CC))[i];

            const bool dogx = (c < NC);
            const int  cc   = c - 2;
            const bool dol1 = (cc >= 0);

            if (dogx && dol1) {
                // ---- common fused path (508 of 514 iterations) ----
                const float* xs = &s_x[bs][c & 1][0][0];
                float* go = &s_gx0[bs][c & 1][0][0];
                const float* gx = &s_gx1[bs][cc & 1][0][0];
#pragma unroll 2
                for (int s = 0; s < K; ++s) {
                    float gr = 0.f, gz = 0.f, gn = 0.f;
                    if (act) {
                        gr = gx[s * GG + i];
                        gz = gx[s * GG + HH + i];
                        gn = gx[s * GG + 2 * HH + i];
                    }
                    // layer-1 recurrence dot (critical chain)
                    u64 ar = pack2(br, 0.f), az = pack2(bz, 0.f), an = pack2(bn, 0.f);
#pragma unroll
                    for (int k = 0; k < 10; ++k) {
                        fma2(ar, wh[k],      hp[k]);
                        fma2(az, wh[10 + k], hp[k]);
                        fma2(an, wh[20 + k], hp[k]);
                    }
                    // fused gx0 (chain-independent filler)
                    {
                        u64 qr = pack2(xr_, 0.f), qz = pack2(xz_, 0.f), qn = pack2(xn_, 0.f);
                        const float* xrow = xs + s * CC;
#pragma unroll
                        for (int k = 0; k < 8; ++k) {
                            u64 xv = *(const u64*)(xrow + 2 * k);
                            fma2(qr, wp[k],      xv);
                            fma2(qz, wp[8 + k],  xv);
                            fma2(qn, wp[16 + k], xv);
                        }
                        if (act) {
                            go[s * GG + i]          = hsum2(qr);
                            go[s * GG + HH + i]     = hsum2(qz);
                            go[s * GG + 2 * HH + i] = hsum2(qn);
                        }
                    }
                    const float r = siga(gr + hsum2(ar));
                    const float z = siga(gz + hsum2(az));
                    const float n = tanha(fmaf(r, hsum2(an), gn));
                    h = fmaf(z, h - n, n);
#pragma unroll
                    for (int k = 0; k < 10; ++k)
                        hp[k] = pack2(__shfl_sync(FULL, h, 2 * k),
                                      __shfl_sync(FULL, h, 2 * k + 1));
                    // output head (off-chain)
                    float v = h * wo;
                    v += __shfl_down_sync(FULL, v, 16);
                    v += __shfl_down_sync(FULL, v, 8);
                    v += __shfl_down_sync(FULL, v, 4);
                    v += __shfl_down_sync(FULL, v, 2);
                    v += __shfl_down_sync(FULL, v, 1);
                    if (i == 0) ob[cc * K + s] = v + bo;
                }
            } else if (dogx) {
                // ---- warmup: gx0 only ----
                const float* xs = &s_x[bs][c & 1][0][0];
                float* go = &s_gx0[bs][c & 1][0][0];
#pragma unroll 2
                for (int s = 0; s < K; ++s) {
                    u64 qr = pack2(xr_, 0.f), qz = pack2(xz_, 0.f), qn = pack2(xn_, 0.f);
                    const float* xrow = xs + s * CC;
#pragma unroll
                    for (int k = 0; k < 8; ++k) {
                        u64 xv = *(const u64*)(xrow + 2 * k);
                        fma2(qr, wp[k],      xv);
                        fma2(qz, wp[8 + k],  xv);
                        fma2(qn, wp[16 + k], xv);
                    }
                    if (act) {
                        go[s * GG + i]          = hsum2(qr);
                        go[s * GG + HH + i]     = hsum2(qz);
                        go[s * GG + 2 * HH + i] = hsum2(qn);
                    }
                }
            } else if (dol1) {
                // ---- drain: L1 only ----
                const float* gx = &s_gx1[bs][cc & 1][0][0];
#pragma unroll 2
                for (int s = 0; s < K; ++s) {
                    float gr = 0.f, gz = 0.f, gn = 0.f;
                    if (act) {
                        gr = gx[s * GG + i];
                        gz = gx[s * GG + HH + i];
                        gn = gx[s * GG + 2 * HH + i];
                    }
                    u64 ar = pack2(br, 0.f), az = pack2(bz, 0.f), an = pack2(bn, 0.f);
#pragma unroll
                    for (int k = 0; k < 10; ++k) {
                        fma2(ar, wh[k],      hp[k]);
                        fma2(az, wh[10 + k], hp[k]);
                        fma2(an, wh[20 + k], hp[k]);
                    }
                    const float r = siga(gr + hsum2(ar));
                    const float z = siga(gz + hsum2(az));
                    const float n = tanha(fmaf(r, hsum2(an), gn));
                    h = fmaf(z, h - n, n);
#pragma unroll
                    for (int k = 0; k < 10; ++k)
                        hp[k] = pack2(__shfl_sync(FULL, h, 2 * k),
                                      __shfl_sync(FULL, h, 2 * k + 1));
                    float v = h * wo;
                    v += __shfl_down_sync(FULL, v, 16);
                    v += __shfl_down_sync(FULL, v, 8);
                    v += __shfl_down_sync(FULL, v, 4);
                    v += __shfl_down_sync(FULL, v, 2);
                    v += __shfl_down_sync(FULL, v, 1);
                    if (i == 0) ob[cc * K + s] = v + bo;
                }
            }

            // deposit prefetched x chunk (LDG latency hidden by the whole iter)
            if (pf) ((float4*)&s_x[bs][(c + 1) & 1][0][0])[i] = xpref;
            __syncthreads();
        }
        if (act) out[(size_t)BB * TT + (b * 2 + 1) * HH + i] = h;
    }
}

// ---------------------------------------------------------------------------
extern "C" void kernel_launch(void* const* d_in, const int* in_sizes, int n_in,
                              void* d_out, int out_size) {
    const float* x     = (const float*)d_in[0];
    const float* h0    = (const float*)d_in[1];
    const float* W_ih0 = (const float*)d_in[2];
    const float* W_hh0 = (const float*)d_in[3];
    const float* b_ih0 = (const float*)d_in[4];
    const float* b_hh0 = (const float*)d_in[5];
    const float* W_ih1 = (const float*)d_in[6];
    const float* W_hh1 = (const float*)d_in[7];
    const float* b_ih1 = (const float*)d_in[8];
    const float* b_hh1 = (const float*)d_in[9];
    const float* W_o   = (const float*)d_in[10];
    const float* b_o   = (const float*)d_in[11];

    fused_gru_kernel<<<BB / 2, 128>>>(x, h0, W_ih0, W_hh0, b_ih0, b_hh0,
                                      W_ih1, W_hh1, b_ih1, b_hh1, W_o, b_o,
                                      (float*)d_out);
}